// round 10
// baseline (speedup 1.0000x reference)
#include <cuda_runtime.h>
#include <cstdint>

// Problem: B=8, L=256, Z=16, H=256. Reassociated (12.9 GFLOP):
//   A: Wc[bz][i][j] = sum_o cls[bz][o] * W[i][o][j]
//   B: t[b][x*16+z][j] = sum_i start[b][x][i] * Wc[bz][i][j]
//   C: out[b][x][y][z] = sum_j t[b][m][j] * end[b][y][j]
// All stages: tf32 mma.sync m16n8k8, 3-term split (hi*hi + hi*lo + lo*hi).
// Inter-stage tensors stored pre-split as tf32 hi/lo u32 arrays.

typedef unsigned u32;
typedef unsigned long long u64;

__device__ u32 g_clsh[32768],  g_clsl[32768];    // cls   [bz=128][o=256]
__device__ u32 g_sth[524288],  g_stl[524288];    // start [b][x][i]
__device__ u32 g_endh[524288], g_endl[524288];   // end   [b][y][j]
__device__ u32 g_wch[8388608], g_wcl[8388608];   // Wc    [bz][i][j]
__device__ u32 g_th[8388608],  g_tl[8388608];    // t     [b][m=4096][j]

__device__ __forceinline__ u32 f2tf(float f) {
    u32 u; asm("cvt.rna.tf32.f32 %0, %1;" : "=r"(u) : "f"(f)); return u;
}
__device__ __forceinline__ void mma_tf32(float d[4], u32 a0, u32 a1, u32 a2, u32 a3,
                                         u32 b0, u32 b1)
{
    asm volatile(
        "mma.sync.aligned.m16n8k8.row.col.f32.tf32.tf32.f32 "
        "{%0,%1,%2,%3}, {%4,%5,%6,%7}, {%8,%9}, {%0,%1,%2,%3};"
        : "+f"(d[0]), "+f"(d[1]), "+f"(d[2]), "+f"(d[3])
        : "r"(a0), "r"(a1), "r"(a2), "r"(a3), "r"(b0), "r"(b1));
}

#define PAD 136   // 136 % 32 == 8 -> fragment LDS bank = (8k + col) % 32, conflict-free

// Fragment loads + 48 MMAs for one k=8 chunk. Layout validated in R9.
__device__ __forceinline__ void mma_phase(const u32 (*AsH)[PAD], const u32 (*AsL)[PAD],
                                          const u32 (*WsH)[PAD], const u32 (*WsL)[PAD],
                                          int lane, int wm, int wn, float acc[2][8][4])
{
    int fr = lane >> 2, fk = lane & 3;
    u32 ah[2][4], al[2][4];
#pragma unroll
    for (int mb = 0; mb < 2; mb++) {
        int m = wm + mb * 16 + fr;
        ah[mb][0] = AsH[fk][m];     ah[mb][1] = AsH[fk][m + 8];
        ah[mb][2] = AsH[fk + 4][m]; ah[mb][3] = AsH[fk + 4][m + 8];
        al[mb][0] = AsL[fk][m];     al[mb][1] = AsL[fk][m + 8];
        al[mb][2] = AsL[fk + 4][m]; al[mb][3] = AsL[fk + 4][m + 8];
    }
#pragma unroll
    for (int nb = 0; nb < 8; nb++) {
        int n = wn + nb * 8 + fr;
        u32 bh0 = WsH[fk][n], bh1 = WsH[fk + 4][n];
        u32 bl0 = WsL[fk][n], bl1 = WsL[fk + 4][n];
#pragma unroll
        for (int mb = 0; mb < 2; mb++) {
            mma_tf32(acc[mb][nb], ah[mb][0], ah[mb][1], ah[mb][2], ah[mb][3], bh0, bh1);
            mma_tf32(acc[mb][nb], ah[mb][0], ah[mb][1], ah[mb][2], ah[mb][3], bl0, bl1);
            mma_tf32(acc[mb][nb], al[mb][0], al[mb][1], al[mb][2], al[mb][3], bh0, bh1);
        }
    }
}

__device__ __forceinline__ u64 split_pair(float v0, float v1, u64& lopair) {
    u32 h0 = f2tf(v0), h1 = f2tf(v1);
    u32 l0 = f2tf(v0 - __uint_as_float(h0));
    u32 l1 = f2tf(v1 - __uint_as_float(h1));
    lopair = ((u64)l1 << 32) | l0;
    return ((u64)h1 << 32) | h0;
}

// --------------------------- input split prepass ---------------------------
__global__ void split_inputs(const float* __restrict__ cls,
                             const float* __restrict__ start,
                             const float* __restrict__ endl)
{
    long idx = (long)blockIdx.x * 256 + threadIdx.x;
    const float* src; u32 *dh, *dl; long off;
    if (idx < 32768)            { src = cls;   dh = g_clsh; dl = g_clsl; off = idx; }
    else if (idx < 32768 + 524288) { src = start; dh = g_sth;  dl = g_stl;  off = idx - 32768; }
    else                        { src = endl;  dh = g_endh; dl = g_endl; off = idx - 32768 - 524288; }
    float f = src[off];
    u32 h = f2tf(f);
    dh[off] = h;
    dl[off] = f2tf(f - __uint_as_float(h));
}

// ---------------------------------------------------------------------------
// kernA: per (j-half, i): Wc[bz=128][j=128], K=o=256. A=cls (pre-split),
// B=W (fp32, split in-kernel; W is read exactly once so no pre-pass).
// Epilogue writes Wc as tf32 hi/lo pairs.
// ---------------------------------------------------------------------------
__global__ __launch_bounds__(256, 2)
void kernA_mma(const float* __restrict__ W)
{
    __shared__ u32 AsH[8][PAD], AsL[8][PAD], WsH[8][PAD], WsL[8][PAD];
    int tid = threadIdx.x, lane = tid & 31, wid = tid >> 5;
    int j0 = blockIdx.x * 128, i_dim = blockIdx.z;
    int wm = (wid & 3) * 32, wn = (wid >> 2) * 64;
    const float* Wi = W + (long)i_dim * 65536;

    float acc[2][8][4];
#pragma unroll
    for (int mb = 0; mb < 2; mb++)
#pragma unroll
        for (int nb = 0; nb < 8; nb++)
#pragma unroll
            for (int q = 0; q < 4; q++) acc[mb][nb][q] = 0.f;

    int rr = tid >> 5, cc = (tid & 31) * 4;   // W loader
    int cm = tid >> 1, ckq = (tid & 1) * 4;   // cls loader

    float4 wv = *(const float4*)(Wi + (long)rr * 256 + j0 + cc);
    uint4 vh = *(const uint4*)(g_clsh + (long)cm * 256 + ckq);
    uint4 vl = *(const uint4*)(g_clsl + (long)cm * 256 + ckq);

    for (int c = 0; c < 32; c++) {
        {
            float fs[4] = {wv.x, wv.y, wv.z, wv.w};
            u32 hh[4], ll[4];
#pragma unroll
            for (int e = 0; e < 4; e++) {
                hh[e] = f2tf(fs[e]);
                ll[e] = f2tf(fs[e] - __uint_as_float(hh[e]));
            }
            *(uint4*)&WsH[rr][cc] = make_uint4(hh[0], hh[1], hh[2], hh[3]);
            *(uint4*)&WsL[rr][cc] = make_uint4(ll[0], ll[1], ll[2], ll[3]);
            AsH[ckq + 0][cm] = vh.x; AsH[ckq + 1][cm] = vh.y;
            AsH[ckq + 2][cm] = vh.z; AsH[ckq + 3][cm] = vh.w;
            AsL[ckq + 0][cm] = vl.x; AsL[ckq + 1][cm] = vl.y;
            AsL[ckq + 2][cm] = vl.z; AsL[ckq + 3][cm] = vl.w;
        }
        __syncthreads();
        if (c + 1 < 32) {
            int k1 = (c + 1) * 8;
            wv = *(const float4*)(Wi + (long)(k1 + rr) * 256 + j0 + cc);
            vh = *(const uint4*)(g_clsh + (long)cm * 256 + k1 + ckq);
            vl = *(const uint4*)(g_clsl + (long)cm * 256 + k1 + ckq);
        }
        mma_phase(AsH, AsL, WsH, WsL, lane, wm, wn, acc);
        __syncthreads();
    }

    int fr = lane >> 2, fc = (lane & 3) * 2;
#pragma unroll
    for (int mb = 0; mb < 2; mb++) {
#pragma unroll
        for (int nb = 0; nb < 8; nb++) {
            long m = wm + mb * 16 + fr;                 // bz row
            long j = j0 + wn + nb * 8 + fc;
            long p0 = m * 65536 + (long)i_dim * 256 + j;
            long p1 = p0 + 8 * 65536;                   // row m+8
            u64 lp;
            u64 hp = split_pair(acc[mb][nb][0], acc[mb][nb][1], lp);
            *(u64*)(g_wch + p0) = hp; *(u64*)(g_wcl + p0) = lp;
            hp = split_pair(acc[mb][nb][2], acc[mb][nb][3], lp);
            *(u64*)(g_wch + p1) = hp; *(u64*)(g_wcl + p1) = lp;
        }
    }
}

// ---------------------------------------------------------------------------
// kernB: per bz: t tile, M=x(256), N=j(256), K=i(256). Both operands pre-split.
// Epilogue writes t[b][m=x*16+z][j] as tf32 hi/lo pairs.
// ---------------------------------------------------------------------------
__global__ __launch_bounds__(256, 2)
void kernB_mma()
{
    __shared__ u32 AsH[8][PAD], AsL[8][PAD], WsH[8][PAD], WsL[8][PAD];
    int tid = threadIdx.x, lane = tid & 31, wid = tid >> 5;
    int j0 = blockIdx.x * 128, m0 = blockIdx.y * 128;
    int bz = blockIdx.z, b = bz >> 4, z = bz & 15;
    int wm = (wid & 3) * 32, wn = (wid >> 2) * 64;

    const u32* aH = g_sth + (long)b * 65536;    // [x][i]
    const u32* aL = g_stl + (long)b * 65536;
    const u32* bH = g_wch + (long)bz * 65536;   // [i][j]
    const u32* bL = g_wcl + (long)bz * 65536;

    float acc[2][8][4];
#pragma unroll
    for (int mb = 0; mb < 2; mb++)
#pragma unroll
        for (int nb = 0; nb < 8; nb++)
#pragma unroll
            for (int q = 0; q < 4; q++) acc[mb][nb][q] = 0.f;

    int rr = tid >> 5, cc = (tid & 31) * 4;
    int cm = tid >> 1, ckq = (tid & 1) * 4;

    uint4 avh = *(const uint4*)(aH + (long)(m0 + cm) * 256 + ckq);
    uint4 avl = *(const uint4*)(aL + (long)(m0 + cm) * 256 + ckq);
    uint4 bvh = *(const uint4*)(bH + (long)rr * 256 + j0 + cc);
    uint4 bvl = *(const uint4*)(bL + (long)rr * 256 + j0 + cc);

    for (int c = 0; c < 32; c++) {
        *(uint4*)&WsH[rr][cc] = bvh;
        *(uint4*)&WsL[rr][cc] = bvl;
        AsH[ckq + 0][cm] = avh.x; AsH[ckq + 1][cm] = avh.y;
        AsH[ckq + 2][cm] = avh.z; AsH[ckq + 3][cm] = avh.w;
        AsL[ckq + 0][cm] = avl.x; AsL[ckq + 1][cm] = avl.y;
        AsL[ckq + 2][cm] = avl.z; AsL[ckq + 3][cm] = avl.w;
        __syncthreads();
        if (c + 1 < 32) {
            int k1 = (c + 1) * 8;
            avh = *(const uint4*)(aH + (long)(m0 + cm) * 256 + k1 + ckq);
            avl = *(const uint4*)(aL + (long)(m0 + cm) * 256 + k1 + ckq);
            bvh = *(const uint4*)(bH + (long)(k1 + rr) * 256 + j0 + cc);
            bvl = *(const uint4*)(bL + (long)(k1 + rr) * 256 + j0 + cc);
        }
        mma_phase(AsH, AsL, WsH, WsL, lane, wm, wn, acc);
        __syncthreads();
    }

    int fr = lane >> 2, fc = (lane & 3) * 2;
#pragma unroll
    for (int mb = 0; mb < 2; mb++) {
#pragma unroll
        for (int nb = 0; nb < 8; nb++) {
            long x = m0 + wm + mb * 16 + fr;
            long j = j0 + wn + nb * 8 + fc;
            long p0 = ((long)b * 4096 + x * 16 + z) * 256 + j;
            long p1 = ((long)b * 4096 + (x + 8) * 16 + z) * 256 + j;
            u64 lp;
            u64 hp = split_pair(acc[mb][nb][0], acc[mb][nb][1], lp);
            *(u64*)(g_th + p0) = hp; *(u64*)(g_tl + p0) = lp;
            hp = split_pair(acc[mb][nb][2], acc[mb][nb][3], lp);
            *(u64*)(g_th + p1) = hp; *(u64*)(g_tl + p1) = lp;
        }
    }
}

// ---------------------------------------------------------------------------
// kernC: per b: out, M=m(4096), N=y(256), K=j(256). A=t (pre-split),
// B=end (pre-split, transposed into smem). Output fp32 to out[b][x][y][z].
// ---------------------------------------------------------------------------
__global__ __launch_bounds__(256, 2)
void kernC_mma(float* __restrict__ out)
{
    __shared__ u32 AsH[8][PAD], AsL[8][PAD], WsH[8][PAD], WsL[8][PAD];
    int tid = threadIdx.x, lane = tid & 31, wid = tid >> 5;
    int n0 = blockIdx.x * 128, m0 = blockIdx.y * 128;
    int b = blockIdx.z;
    int wm = (wid & 3) * 32, wn = (wid >> 2) * 64;

    const u32* aH = g_th + (long)b * 1048576;    // [m][j]
    const u32* aL = g_tl + (long)b * 1048576;
    const u32* eH = g_endh + (long)b * 65536;    // [y][j]
    const u32* eL = g_endl + (long)b * 65536;
    float* O = out + (long)b * 1048576;

    float acc[2][8][4];
#pragma unroll
    for (int mb = 0; mb < 2; mb++)
#pragma unroll
        for (int nb = 0; nb < 8; nb++)
#pragma unroll
            for (int q = 0; q < 4; q++) acc[mb][nb][q] = 0.f;

    int cm = tid >> 1, ckq = (tid & 1) * 4;      // A loader (m rows)
    int yy = tid >> 1, jq = (tid & 1) * 4;       // B loader (y rows, transpose store)

    uint4 avh = *(const uint4*)(aH + (long)(m0 + cm) * 256 + ckq);
    uint4 avl = *(const uint4*)(aL + (long)(m0 + cm) * 256 + ckq);
    uint4 evh = *(const uint4*)(eH + (long)(n0 + yy) * 256 + jq);
    uint4 evl = *(const uint4*)(eL + (long)(n0 + yy) * 256 + jq);

    for (int c = 0; c < 32; c++) {
        AsH[ckq + 0][cm] = avh.x; AsH[ckq + 1][cm] = avh.y;
        AsH[ckq + 2][cm] = avh.z; AsH[ckq + 3][cm] = avh.w;
        AsL[ckq + 0][cm] = avl.x; AsL[ckq + 1][cm] = avl.y;
        AsL[ckq + 2][cm] = avl.z; AsL[ckq + 3][cm] = avl.w;
        WsH[jq + 0][yy] = evh.x;  WsH[jq + 1][yy] = evh.y;
        WsH[jq + 2][yy] = evh.z;  WsH[jq + 3][yy] = evh.w;
        WsL[jq + 0][yy] = evl.x;  WsL[jq + 1][yy] = evl.y;
        WsL[jq + 2][yy] = evl.z;  WsL[jq + 3][yy] = evl.w;
        __syncthreads();
        if (c + 1 < 32) {
            int k1 = (c + 1) * 8;
            avh = *(const uint4*)(aH + (long)(m0 + cm) * 256 + k1 + ckq);
            avl = *(const uint4*)(aL + (long)(m0 + cm) * 256 + k1 + ckq);
            evh = *(const uint4*)(eH + (long)(n0 + yy) * 256 + k1 + jq);
            evl = *(const uint4*)(eL + (long)(n0 + yy) * 256 + k1 + jq);
        }
        mma_phase(AsH, AsL, WsH, WsL, lane, wm, wn, acc);
        __syncthreads();
    }

    int fr = lane >> 2, fc = (lane & 3) * 2;
#pragma unroll
    for (int mb = 0; mb < 2; mb++) {
#pragma unroll
        for (int nb = 0; nb < 8; nb++) {
            int m  = m0 + wm + mb * 16 + fr;
            long y = n0 + wn + nb * 8 + fc;
            long x = m >> 4;  int zz = m & 15;
            O[x * 4096 + y * 16 + zz]       = acc[mb][nb][0];
            O[x * 4096 + (y + 1) * 16 + zz] = acc[mb][nb][1];
            int m2 = m + 8;
            long x2 = m2 >> 4; int z2 = m2 & 15;
            O[x2 * 4096 + y * 16 + z2]       = acc[mb][nb][2];
            O[x2 * 4096 + (y + 1) * 16 + z2] = acc[mb][nb][3];
        }
    }
}

// ===================== launch ================================================
extern "C" void kernel_launch(void* const* d_in, const int* in_sizes, int n_in,
                              void* d_out, int out_size)
{
    const float* start = (const float*)d_in[0];   // [8,256,256]
    const float* endl  = (const float*)d_in[1];   // [8,256,256]
    const float* cls   = (const float*)d_in[2];   // [8,16,256]
    const float* W     = (const float*)d_in[3];   // [256,256,256]
    float* out = (float*)d_out;                   // [8,256,256,16]

    split_inputs<<<4224, 256>>>(cls, start, endl);

    dim3 gA(2, 1, 256);      // j-half, -, i
    kernA_mma<<<gA, 256>>>(W);

    dim3 gB(2, 2, 128);      // j, x, bz
    kernB_mma<<<gB, 256>>>();

    dim3 gC(2, 32, 8);       // y, m, b
    kernC_mma<<<gC, 256>>>(out);
}

// round 11
// speedup vs baseline: 2.5068x; 2.5068x over previous
#include <cuda_runtime.h>
#include <cuda_bf16.h>
#include <cstdint>

// Problem: B=8, L=256, Z=16, H=256. Reassociated (12.9 GFLOP):
//   A: Wc[bz][i][j] = sum_o cls[bz][o] * W[i][o][j]
//   B: t[b][x*16+z][j] = sum_i start[b][x][i] * Wc[bz][i][j]
//   C: out[b][x][y][z] = sum_j t[b][m][j] * end[b][y][j]
// All stages: bf16 mma.sync m16n8k16, 3-term split (hi*hi + hi*lo + lo*hi).
// Operands stored as packed bf16-pair (along k) hi/lo u32 arrays.

typedef unsigned u32;
typedef unsigned long long u64;

__device__ u32 g_clsh[16384],   g_clsl[16384];    // cls  [bz=128][op=128]
__device__ u32 g_sth[262144],   g_stl[262144];    // start[b*x=2048][ip=128]
__device__ u32 g_endh[262144],  g_endl[262144];   // end  [b*y=2048][jp=128]
__device__ float g_wc[8388608];                   // Wc   [bz][i][j] fp32
__device__ u32 g_wcth[4194304], g_wctl[4194304];  // Wc^T [bz][j=256][ip=128]
__device__ u32 g_th[4194304],   g_tl[4194304];    // t    [b*m=32768][jp=128]

// ---------------- bf16 helpers --------------------------------------------
__device__ __forceinline__ u32 packbf(__nv_bfloat16 e0, __nv_bfloat16 e1) {
    return ((u32)__bfloat16_as_ushort(e1) << 16) | (u32)__bfloat16_as_ushort(e0);
}
// split pair (f0=k even, f1=k odd) -> hi-pair u32, lo-pair u32
__device__ __forceinline__ u32 packsplit(float f0, float f1, u32& lo) {
    __nv_bfloat16 h0 = __float2bfloat16_rn(f0), h1 = __float2bfloat16_rn(f1);
    float r0 = f0 - __bfloat162float(h0), r1 = f1 - __bfloat162float(h1);
    lo = packbf(__float2bfloat16_rn(r0), __float2bfloat16_rn(r1));
    return packbf(h0, h1);
}
__device__ __forceinline__ void mma_bf16(float d[4], u32 a0, u32 a1, u32 a2, u32 a3,
                                         u32 b0, u32 b1)
{
    asm volatile(
        "mma.sync.aligned.m16n8k16.row.col.f32.bf16.bf16.f32 "
        "{%0,%1,%2,%3}, {%4,%5,%6,%7}, {%8,%9}, {%0,%1,%2,%3};"
        : "+f"(d[0]), "+f"(d[1]), "+f"(d[2]), "+f"(d[3])
        : "r"(a0), "r"(a1), "r"(a2), "r"(a3), "r"(b0), "r"(b1));
}

#define PAD 136   // (8*kp + col) % 32 distinct per lane group -> conflict-free

// One k=16 chunk: fragment loads + 48 MMAs. kp = k/2 (u32 holds bf16 pair).
// A frag: a0:(r,kp) a1:(r+8,kp) a2:(r,kp+4) a3:(r+8,kp+4); r=lane/4, kp=lane%4.
// B frag: b0:(kp,n) b1:(kp+4,n); n=lane/4.
__device__ __forceinline__ void mma_phase(const u32 (*AsH)[PAD], const u32 (*AsL)[PAD],
                                          const u32 (*WsH)[PAD], const u32 (*WsL)[PAD],
                                          int lane, int wm, int wn, float acc[2][8][4])
{
    int fr = lane >> 2, fk = lane & 3;
    u32 ah[2][4], al[2][4];
#pragma unroll
    for (int mb = 0; mb < 2; mb++) {
        int m = wm + mb * 16 + fr;
        ah[mb][0] = AsH[fk][m];     ah[mb][1] = AsH[fk][m + 8];
        ah[mb][2] = AsH[fk + 4][m]; ah[mb][3] = AsH[fk + 4][m + 8];
        al[mb][0] = AsL[fk][m];     al[mb][1] = AsL[fk][m + 8];
        al[mb][2] = AsL[fk + 4][m]; al[mb][3] = AsL[fk + 4][m + 8];
    }
#pragma unroll
    for (int nb = 0; nb < 8; nb++) {
        int n = wn + nb * 8 + fr;
        u32 bh0 = WsH[fk][n], bh1 = WsH[fk + 4][n];
        u32 bl0 = WsL[fk][n], bl1 = WsL[fk + 4][n];
#pragma unroll
        for (int mb = 0; mb < 2; mb++) {
            mma_bf16(acc[mb][nb], ah[mb][0], ah[mb][1], ah[mb][2], ah[mb][3], bh0, bh1);
            mma_bf16(acc[mb][nb], ah[mb][0], ah[mb][1], ah[mb][2], ah[mb][3], bl0, bl1);
            mma_bf16(acc[mb][nb], al[mb][0], al[mb][1], al[mb][2], al[mb][3], bh0, bh1);
        }
    }
}

// --------------------------- input split prepass ---------------------------
// Packs pairs along the last (k) dimension. 540672 pairs total.
__global__ void split_inputs(const float* __restrict__ cls,
                             const float* __restrict__ start,
                             const float* __restrict__ endl)
{
    long p = (long)blockIdx.x * 256 + threadIdx.x;
    const float* src; u32 *dh, *dl; long off;
    if (p < 16384)              { src = cls;   dh = g_clsh; dl = g_clsl; off = p; }
    else if (p < 16384 + 262144){ src = start; dh = g_sth;  dl = g_stl;  off = p - 16384; }
    else if (p < 16384 + 524288){ src = endl;  dh = g_endh; dl = g_endl; off = p - 16384 - 262144; }
    else return;
    float f0 = src[off * 2], f1 = src[off * 2 + 1];
    u32 lo; u32 hi = packsplit(f0, f1, lo);
    dh[off] = hi; dl[off] = lo;
}

// ---------------------------------------------------------------------------
// kernA: per (j-half, i): Wc[bz=128][j=128] over K=o=256 (16 chunks of k16).
// A = cls (packed o-pairs). B = W fp32, split+packed in-kernel.
// Epilogue: plain fp32 Wc (repack kernel transposes+splits it for kernB).
// ---------------------------------------------------------------------------
__global__ __launch_bounds__(256, 2)
void kernA_mma(const float* __restrict__ W)
{
    __shared__ u32 AsH[8][PAD], AsL[8][PAD], WsH[8][PAD], WsL[8][PAD];
    int tid = threadIdx.x, lane = tid & 31, wid = tid >> 5;
    int j0 = blockIdx.x * 128, i_dim = blockIdx.z;
    int wm = (wid & 3) * 32, wn = (wid >> 2) * 64;
    const float* Wi = W + (long)i_dim * 65536;   // [o=256][j=256]

    float acc[2][8][4];
#pragma unroll
    for (int mb = 0; mb < 2; mb++)
#pragma unroll
        for (int nb = 0; nb < 8; nb++)
#pragma unroll
            for (int q = 0; q < 4; q++) acc[mb][nb][q] = 0.f;

    int kp = tid >> 5;            // 0..7: o-pair row within chunk
    int j4 = (tid & 31) * 4;      // 4 j columns
    int cm = tid >> 1, ckq = (tid & 1) * 4;   // cls loader: row bz, 4 op's

    float4 w0 = *(const float4*)(Wi + (long)(2 * kp) * 256 + j0 + j4);
    float4 w1 = *(const float4*)(Wi + (long)(2 * kp + 1) * 256 + j0 + j4);
    uint4 vh = *(const uint4*)(g_clsh + (long)cm * 128 + ckq);
    uint4 vl = *(const uint4*)(g_clsl + (long)cm * 128 + ckq);

    for (int c = 0; c < 16; c++) {
        {
            float e0[4] = {w0.x, w0.y, w0.z, w0.w};
            float e1[4] = {w1.x, w1.y, w1.z, w1.w};
            u32 hh[4], ll[4];
#pragma unroll
            for (int e = 0; e < 4; e++) hh[e] = packsplit(e0[e], e1[e], ll[e]);
            *(uint4*)&WsH[kp][j4] = make_uint4(hh[0], hh[1], hh[2], hh[3]);
            *(uint4*)&WsL[kp][j4] = make_uint4(ll[0], ll[1], ll[2], ll[3]);
            AsH[ckq + 0][cm] = vh.x; AsH[ckq + 1][cm] = vh.y;
            AsH[ckq + 2][cm] = vh.z; AsH[ckq + 3][cm] = vh.w;
            AsL[ckq + 0][cm] = vl.x; AsL[ckq + 1][cm] = vl.y;
            AsL[ckq + 2][cm] = vl.z; AsL[ckq + 3][cm] = vl.w;
        }
        __syncthreads();
        if (c + 1 < 16) {
            int o1 = (c + 1) * 16;
            w0 = *(const float4*)(Wi + (long)(o1 + 2 * kp) * 256 + j0 + j4);
            w1 = *(const float4*)(Wi + (long)(o1 + 2 * kp + 1) * 256 + j0 + j4);
            int kp1 = (c + 1) * 8;
            vh = *(const uint4*)(g_clsh + (long)cm * 128 + kp1 + ckq);
            vl = *(const uint4*)(g_clsl + (long)cm * 128 + kp1 + ckq);
        }
        mma_phase(AsH, AsL, WsH, WsL, lane, wm, wn, acc);
        __syncthreads();
    }

    int fr = lane >> 2, fc = (lane & 3) * 2;
#pragma unroll
    for (int mb = 0; mb < 2; mb++) {
#pragma unroll
        for (int nb = 0; nb < 8; nb++) {
            long m = wm + mb * 16 + fr;
            long j = j0 + wn + nb * 8 + fc;
            float* p0 = g_wc + m * 65536 + (long)i_dim * 256 + j;
            float* p1 = p0 + 8 * 65536;
            *(float2*)p0 = make_float2(acc[mb][nb][0], acc[mb][nb][1]);
            *(float2*)p1 = make_float2(acc[mb][nb][2], acc[mb][nb][3]);
        }
    }
}

// ---------------------------------------------------------------------------
// repack: Wc fp32 [bz][i][j] -> Wc^T packed bf16 pairs [bz][j][ip=128] hi/lo.
// ---------------------------------------------------------------------------
__global__ void repack_wc()
{
    __shared__ float T[32][33];
    int bz = blockIdx.z, i0 = blockIdx.y * 32, j0 = blockIdx.x * 32;
    const float* src = g_wc + (long)bz * 65536;
    int t = threadIdx.x;
    int jj = t & 31, g = t >> 5;
#pragma unroll
    for (int rr = 0; rr < 4; rr++) {
        int ii = g * 4 + rr;
        T[ii][jj] = src[(long)(i0 + ii) * 256 + j0 + jj];
    }
    __syncthreads();
#pragma unroll
    for (int it = 0; it < 2; it++) {
        int s = t + it * 256;
        int jr = s >> 4, ip = s & 15;
        u32 lo; u32 hi = packsplit(T[ip * 2][jr], T[ip * 2 + 1][jr], lo);
        long idx = (long)bz * 32768 + (long)(j0 + jr) * 128 + (i0 >> 1) + ip;
        g_wcth[idx] = hi; g_wctl[idx] = lo;
    }
}

// ---------------------------------------------------------------------------
// kernB: per bz: D[x=128][j=128] over K=i=256 (16 chunks).
// A = start packed [x][ip]. B = Wc^T packed [j][ip].
// Epilogue: t[b][x*16+z][jp] packed hi/lo (j-pairs native from fragment quad).
// ---------------------------------------------------------------------------
__global__ __launch_bounds__(256, 2)
void kernB_mma()
{
    __shared__ u32 AsH[8][PAD], AsL[8][PAD], WsH[8][PAD], WsL[8][PAD];
    int tid = threadIdx.x, lane = tid & 31, wid = tid >> 5;
    int j0 = blockIdx.x * 128, m0 = blockIdx.y * 128;
    int bz = blockIdx.z, b = bz >> 4, z = bz & 15;
    int wm = (wid & 3) * 32, wn = (wid >> 2) * 64;

    const u32* aH = g_sth + (long)b * 32768;     // [x][ip=128]
    const u32* aL = g_stl + (long)b * 32768;
    const u32* bH = g_wcth + (long)bz * 32768;   // [j][ip=128]
    const u32* bL = g_wctl + (long)bz * 32768;

    float acc[2][8][4];
#pragma unroll
    for (int mb = 0; mb < 2; mb++)
#pragma unroll
        for (int nb = 0; nb < 8; nb++)
#pragma unroll
            for (int q = 0; q < 4; q++) acc[mb][nb][q] = 0.f;

    int cm = tid >> 1, ckq = (tid & 1) * 4;   // both loaders: row, 4 kp's

    uint4 avh = *(const uint4*)(aH + (long)(m0 + cm) * 128 + ckq);
    uint4 avl = *(const uint4*)(aL + (long)(m0 + cm) * 128 + ckq);
    uint4 bvh = *(const uint4*)(bH + (long)(j0 + cm) * 128 + ckq);
    uint4 bvl = *(const uint4*)(bL + (long)(j0 + cm) * 128 + ckq);

    for (int c = 0; c < 16; c++) {
        AsH[ckq + 0][cm] = avh.x; AsH[ckq + 1][cm] = avh.y;
        AsH[ckq + 2][cm] = avh.z; AsH[ckq + 3][cm] = avh.w;
        AsL[ckq + 0][cm] = avl.x; AsL[ckq + 1][cm] = avl.y;
        AsL[ckq + 2][cm] = avl.z; AsL[ckq + 3][cm] = avl.w;
        WsH[ckq + 0][cm] = bvh.x; WsH[ckq + 1][cm] = bvh.y;
        WsH[ckq + 2][cm] = bvh.z; WsH[ckq + 3][cm] = bvh.w;
        WsL[ckq + 0][cm] = bvl.x; WsL[ckq + 1][cm] = bvl.y;
        WsL[ckq + 2][cm] = bvl.z; WsL[ckq + 3][cm] = bvl.w;
        __syncthreads();
        if (c + 1 < 16) {
            int k1 = (c + 1) * 8;
            avh = *(const uint4*)(aH + (long)(m0 + cm) * 128 + k1 + ckq);
            avl = *(const uint4*)(aL + (long)(m0 + cm) * 128 + k1 + ckq);
            bvh = *(const uint4*)(bH + (long)(j0 + cm) * 128 + k1 + ckq);
            bvl = *(const uint4*)(bL + (long)(j0 + cm) * 128 + k1 + ckq);
        }
        mma_phase(AsH, AsL, WsH, WsL, lane, wm, wn, acc);
        __syncthreads();
    }

    int fr = lane >> 2, fc = (lane & 3) * 2;
#pragma unroll
    for (int mb = 0; mb < 2; mb++) {
#pragma unroll
        for (int nb = 0; nb < 8; nb++) {
            long x = m0 + wm + mb * 16 + fr;
            long jp = (j0 + wn + nb * 8 + fc) >> 1;       // fc even -> exact pair
            long p0 = ((long)b * 4096 + x * 16 + z) * 128 + jp;
            long p1 = ((long)b * 4096 + (x + 8) * 16 + z) * 128 + jp;
            u32 lo; u32 hi = packsplit(acc[mb][nb][0], acc[mb][nb][1], lo);
            g_th[p0] = hi; g_tl[p0] = lo;
            hi = packsplit(acc[mb][nb][2], acc[mb][nb][3], lo);
            g_th[p1] = hi; g_tl[p1] = lo;
        }
    }
}

// ---------------------------------------------------------------------------
// kernC: per b: D[m=128][y=128] over K=j=256 (16 chunks).
// A = t packed [m][jp]. B = end packed [y][jp]. Output fp32 out[b][x][y][z].
// ---------------------------------------------------------------------------
__global__ __launch_bounds__(256, 2)
void kernC_mma(float* __restrict__ out)
{
    __shared__ u32 AsH[8][PAD], AsL[8][PAD], WsH[8][PAD], WsL[8][PAD];
    int tid = threadIdx.x, lane = tid & 31, wid = tid >> 5;
    int n0 = blockIdx.x * 128, m0 = blockIdx.y * 128;
    int b = blockIdx.z;
    int wm = (wid & 3) * 32, wn = (wid >> 2) * 64;

    const u32* aH = g_th + (long)b * 524288;     // [m=4096][jp=128]
    const u32* aL = g_tl + (long)b * 524288;
    const u32* eH = g_endh + (long)b * 32768;    // [y][jp=128]
    const u32* eL = g_endl + (long)b * 32768;
    float* O = out + (long)b * 1048576;

    float acc[2][8][4];
#pragma unroll
    for (int mb = 0; mb < 2; mb++)
#pragma unroll
        for (int nb = 0; nb < 8; nb++)
#pragma unroll
            for (int q = 0; q < 4; q++) acc[mb][nb][q] = 0.f;

    int cm = tid >> 1, ckq = (tid & 1) * 4;

    uint4 avh = *(const uint4*)(aH + (long)(m0 + cm) * 128 + ckq);
    uint4 avl = *(const uint4*)(aL + (long)(m0 + cm) * 128 + ckq);
    uint4 evh = *(const uint4*)(eH + (long)(n0 + cm) * 128 + ckq);
    uint4 evl = *(const uint4*)(eL + (long)(n0 + cm) * 128 + ckq);

    for (int c = 0; c < 16; c++) {
        AsH[ckq + 0][cm] = avh.x; AsH[ckq + 1][cm] = avh.y;
        AsH[ckq + 2][cm] = avh.z; AsH[ckq + 3][cm] = avh.w;
        AsL[ckq + 0][cm] = avl.x; AsL[ckq + 1][cm] = avl.y;
        AsL[ckq + 2][cm] = avl.z; AsL[ckq + 3][cm] = avl.w;
        WsH[ckq + 0][cm] = evh.x; WsH[ckq + 1][cm] = evh.y;
        WsH[ckq + 2][cm] = evh.z; WsH[ckq + 3][cm] = evh.w;
        WsL[ckq + 0][cm] = evl.x; WsL[ckq + 1][cm] = evl.y;
        WsL[ckq + 2][cm] = evl.z; WsL[ckq + 3][cm] = evl.w;
        __syncthreads();
        if (c + 1 < 16) {
            int k1 = (c + 1) * 8;
            avh = *(const uint4*)(aH + (long)(m0 + cm) * 128 + k1 + ckq);
            avl = *(const uint4*)(aL + (long)(m0 + cm) * 128 + k1 + ckq);
            evh = *(const uint4*)(eH + (long)(n0 + cm) * 128 + k1 + ckq);
            evl = *(const uint4*)(eL + (long)(n0 + cm) * 128 + k1 + ckq);
        }
        mma_phase(AsH, AsL, WsH, WsL, lane, wm, wn, acc);
        __syncthreads();
    }

    int fr = lane >> 2, fc = (lane & 3) * 2;
#pragma unroll
    for (int mb = 0; mb < 2; mb++) {
#pragma unroll
        for (int nb = 0; nb < 8; nb++) {
            int m  = m0 + wm + mb * 16 + fr;
            long y = n0 + wn + nb * 8 + fc;
            long x = m >> 4;  int zz = m & 15;
            O[x * 4096 + y * 16 + zz]       = acc[mb][nb][0];
            O[x * 4096 + (y + 1) * 16 + zz] = acc[mb][nb][1];
            int m2 = m + 8;
            long x2 = m2 >> 4; int z2 = m2 & 15;
            O[x2 * 4096 + y * 16 + z2]       = acc[mb][nb][2];
            O[x2 * 4096 + (y + 1) * 16 + z2] = acc[mb][nb][3];
        }
    }
}

// ===================== launch ================================================
extern "C" void kernel_launch(void* const* d_in, const int* in_sizes, int n_in,
                              void* d_out, int out_size)
{
    const float* start = (const float*)d_in[0];   // [8,256,256]
    const float* endl  = (const float*)d_in[1];   // [8,256,256]
    const float* cls   = (const float*)d_in[2];   // [8,16,256]
    const float* W     = (const float*)d_in[3];   // [256,256,256]
    float* out = (float*)d_out;                   // [8,256,256,16]

    split_inputs<<<2112, 256>>>(cls, start, endl);

    dim3 gA(2, 1, 256);      // j-half, -, i
    kernA_mma<<<gA, 256>>>(W);

    dim3 gR(8, 8, 128);      // j-tile, i-tile, bz
    repack_wc<<<gR, 256>>>();

    dim3 gB(2, 2, 128);      // j, x, bz
    kernB_mma<<<gB, 256>>>();

    dim3 gC(2, 32, 8);       // y, m, b
    kernC_mma<<<gC, 256>>>(out);
}